// round 14
// baseline (speedup 1.0000x reference)
#include <cuda_runtime.h>
#include <cuda_fp16.h>
#include <stdint.h>
#include <math.h>

// Problem constants (fixed by setup_inputs)
#define Bq 2
#define Lq 4096
#define Hq 8
#define Dq 64
#define Mq 128
#define Cq 64
#define NCq (Lq / Cq)      // 64 chunks
#define BHq (Bq * Hq)      // 16 sequences

#define RATIO 0.08838834764831845f   // 1/sqrt(128)
#define STAB  1e-3f

// ---------------- scratch (device globals; no runtime allocation) ----------
__device__ __half g_kvh[BHq * NCq * Dq * Mq];  // [bh, c, d, m] -> exclusive prefix (fp16)
__device__ __half g_qph[BHq * Lq * Mq];        // [bh*L + l][m] fp16
__device__ __half g_kph[BHq * Lq * Mq];        // [bh*L + l][m] fp16
__device__ __half g_vth[BHq * NCq * Dq * Cq];  // [bh, c][d][l] fp16
__device__ float  g_ks[BHq * NCq * Mq];        // [bh, c, m] -> exclusive prefix

// ---------------- helpers ----------------
__device__ __forceinline__ uint32_t f2h2(float lo, float hi) {
    __half2 h = __floats2half2_rn(lo, hi);
    return *reinterpret_cast<uint32_t*>(&h);
}
__device__ __forceinline__ void acc2(float* p, uint32_t u) {
    __half2 h = *reinterpret_cast<__half2*>(&u);
    float2 f = __half22float2(h);
    p[0] += f.x; p[1] += f.y;
}
__device__ __forceinline__ float relu_s(float x) { return fmaxf(x * RATIO, 0.f) + STAB; }

// m16n8k16 fp16 mma, fp32 accumulate (D = A*B + D)
__device__ __forceinline__ void mma16(float* c, uint32_t a0, uint32_t a1, uint32_t a2, uint32_t a3,
                                      uint32_t b0, uint32_t b1) {
    asm("mma.sync.aligned.m16n8k16.row.col.f32.f16.f16.f32 "
        "{%0,%1,%2,%3},{%4,%5,%6,%7},{%8,%9},{%0,%1,%2,%3};"
        : "+f"(c[0]), "+f"(c[1]), "+f"(c[2]), "+f"(c[3])
        : "r"(a0), "r"(a1), "r"(a2), "r"(a3), "r"(b0), "r"(b1));
}

// ======================= Kernel 1: proj (qp,kp) + KV^T / ksum ===============
// grid BH*NC, 256 threads (8 warps), 63 KB smem, 3 CTAs/SM.
// smem u32: Xq [64][36] | Xk [64][36] | Ps [128][36] | kpT [128][36] | vT [64][36]
// stage (KV^T [64][68]) aliases Xq+Xk after projections.
#define CKV_SMEM ((2304 + 2304 + 4608 + 4608 + 2304) * 4)
__global__ void __launch_bounds__(256, 3) chunkkv_kernel(
        const float* __restrict__ Q, const float* __restrict__ K,
        const float* __restrict__ V, const float* __restrict__ P) {
    extern __shared__ uint32_t sm[];
    uint32_t* Xq    = sm;               // [64][36]
    uint32_t* Xk    = Xq + 2304;        // [64][36]
    uint32_t* Ps    = Xk + 2304;        // [128][36]
    uint32_t* kpT   = Ps + 4608;        // [128][36] ([m][l])
    uint32_t* vT    = kpT + 4608;       // [64][36]  ([d][l])
    uint32_t* stage = sm;               // alias [64][68] (free after proj)
    __half*   kph = reinterpret_cast<__half*>(kpT);   // stride 72 halves
    __half*   vTh = reinterpret_cast<__half*>(vT);    // stride 72 halves

    int bid = blockIdx.x;
    int bh = bid / NCq, c = bid % NCq;
    int b = bh / Hq, h = bh % Hq;
    int tid = threadIdx.x;
    int lbase = c * Cq;

    for (int i = tid; i < 128 * 16; i += 256) {
        int m = i >> 4, d4 = i & 15;
        float4 v = reinterpret_cast<const float4*>(P)[m * 16 + d4];
        Ps[m * 36 + d4 * 2]     = f2h2(v.x, v.y);
        Ps[m * 36 + d4 * 2 + 1] = f2h2(v.z, v.w);
    }
    for (int i = tid; i < 64 * 16; i += 256) {
        int l = i >> 4, d4 = i & 15;
        int gidx = ((b * Lq + lbase + l) * Hq + h) * 16 + d4;
        float4 q = reinterpret_cast<const float4*>(Q)[gidx];
        Xq[l * 36 + d4 * 2]     = f2h2(q.x, q.y);
        Xq[l * 36 + d4 * 2 + 1] = f2h2(q.z, q.w);
        float4 k = reinterpret_cast<const float4*>(K)[gidx];
        Xk[l * 36 + d4 * 2]     = f2h2(k.x, k.y);
        Xk[l * 36 + d4 * 2 + 1] = f2h2(k.z, k.w);
        float4 vv = reinterpret_cast<const float4*>(V)[gidx];
        vTh[(d4 * 4 + 0) * 72 + l] = __float2half_rn(vv.x);
        vTh[(d4 * 4 + 1) * 72 + l] = __float2half_rn(vv.y);
        vTh[(d4 * 4 + 2) * 72 + l] = __float2half_rn(vv.z);
        vTh[(d4 * 4 + 3) * 72 + l] = __float2half_rn(vv.w);
    }
    __syncthreads();

    int wid = tid >> 5, lane = tid & 31;
    int g = lane >> 2, t = lane & 3;

    // ---- qp/kp = relu(X @ P^T); 8 warps, 32x32 tiles; STG fp16 (+kpT STS) ----
    uint32_t* qpg = reinterpret_cast<uint32_t*>(g_qph) + (size_t)(bh * Lq + lbase) * 64;
    uint32_t* kpg = reinterpret_cast<uint32_t*>(g_kph) + (size_t)(bh * Lq + lbase) * 64;
#pragma unroll
    for (int which = 0; which < 2; which++) {
        uint32_t* src = which ? Xk : Xq;
        uint32_t* dst = which ? kpg : qpg;
        int lt = wid & 1, nq = wid >> 1;       // 2 row-tiles x 4 col-quarters
        int r0 = lt * 32 + g;
        float acc[2][4][4];
#pragma unroll
        for (int rb = 0; rb < 2; rb++)
#pragma unroll
            for (int j = 0; j < 4; j++)
                acc[rb][j][0] = acc[rb][j][1] = acc[rb][j][2] = acc[rb][j][3] = 0.f;
#pragma unroll
        for (int ks16 = 0; ks16 < 4; ks16++) {
            int kw = ks16 * 8;
            uint32_t a[2][4];
            a[0][0] = src[(r0)      * 36 + kw + t];
            a[0][1] = src[(r0 + 8)  * 36 + kw + t];
            a[0][2] = src[(r0)      * 36 + kw + t + 4];
            a[0][3] = src[(r0 + 8)  * 36 + kw + t + 4];
            a[1][0] = src[(r0 + 16) * 36 + kw + t];
            a[1][1] = src[(r0 + 24) * 36 + kw + t];
            a[1][2] = src[(r0 + 16) * 36 + kw + t + 4];
            a[1][3] = src[(r0 + 24) * 36 + kw + t + 4];
#pragma unroll
            for (int j = 0; j < 4; j++) {
                int n = nq * 32 + j * 8 + g;
                uint32_t b0 = Ps[n * 36 + kw + t], b1 = Ps[n * 36 + kw + t + 4];
                mma16(acc[0][j], a[0][0], a[0][1], a[0][2], a[0][3], b0, b1);
                mma16(acc[1][j], a[1][0], a[1][1], a[1][2], a[1][3], b0, b1);
            }
        }
#pragma unroll
        for (int rb = 0; rb < 2; rb++)
#pragma unroll
            for (int j = 0; j < 4; j++) {
                int row0 = lt * 32 + rb * 16 + g, row1 = row0 + 8;
                float v0 = relu_s(acc[rb][j][0]), v1 = relu_s(acc[rb][j][1]);
                float v2 = relu_s(acc[rb][j][2]), v3 = relu_s(acc[rb][j][3]);
                int colw = nq * 16 + j * 4 + t;
                dst[row0 * 64 + colw] = f2h2(v0, v1);
                dst[row1 * 64 + colw] = f2h2(v2, v3);
                if (which) {
                    int col = nq * 32 + j * 8 + 2 * t;
                    kph[col * 72 + row0]       = __float2half_rn(v0);
                    kph[(col + 1) * 72 + row0] = __float2half_rn(v1);
                    kph[col * 72 + row1]       = __float2half_rn(v2);
                    kph[(col + 1) * 72 + row1] = __float2half_rn(v3);
                }
            }
    }
    __syncthreads();

    int cbase = bh * NCq + c;

    // ---- store v^T fp16 (raw; reused by out) ----
    {
        uint4* vtg = reinterpret_cast<uint4*>(g_vth) + (size_t)cbase * 512;
#pragma unroll
        for (int it = 0; it < 2; it++) {
            int i = tid + it * 256;
            int row = i >> 3, q = i & 7;
            vtg[i] = *reinterpret_cast<uint4*>(&vT[row * 36 + q * 4]);
        }
    }

    // ---- ksum[m] = sum_l kp[l][m] ----
    {
        int m = tid >> 1, half = tid & 1;
        float s = 0.f;
        for (int l = 0; l < 32; l++) s += __half2float(kph[m * 72 + half * 32 + l]);
        s += __shfl_xor_sync(0xffffffffu, s, 1);
        if (half == 0) g_ks[cbase * Mq + m] = s;
    }

    // ---- KV^T = v^T @ kp : A = vT [d][l], B = kpT [m][l]; 32x32 tiles ----
    {
        int dt = wid & 1, mq = wid >> 1;
        int d0 = dt * 32 + g;
        float acc[2][4][4];
#pragma unroll
        for (int rb = 0; rb < 2; rb++)
#pragma unroll
            for (int j = 0; j < 4; j++)
                acc[rb][j][0] = acc[rb][j][1] = acc[rb][j][2] = acc[rb][j][3] = 0.f;
#pragma unroll
        for (int ks16 = 0; ks16 < 4; ks16++) {
            int kw = ks16 * 8;
            uint32_t a[2][4];
            a[0][0] = vT[(d0)      * 36 + kw + t];
            a[0][1] = vT[(d0 + 8)  * 36 + kw + t];
            a[0][2] = vT[(d0)      * 36 + kw + t + 4];
            a[0][3] = vT[(d0 + 8)  * 36 + kw + t + 4];
            a[1][0] = vT[(d0 + 16) * 36 + kw + t];
            a[1][1] = vT[(d0 + 24) * 36 + kw + t];
            a[1][2] = vT[(d0 + 16) * 36 + kw + t + 4];
            a[1][3] = vT[(d0 + 24) * 36 + kw + t + 4];
#pragma unroll
            for (int j = 0; j < 4; j++) {
                int n = mq * 32 + j * 8 + g;
                uint32_t b0 = kpT[n * 36 + kw + t], b1 = kpT[n * 36 + kw + t + 4];
                mma16(acc[0][j], a[0][0], a[0][1], a[0][2], a[0][3], b0, b1);
                mma16(acc[1][j], a[1][0], a[1][1], a[1][2], a[1][3], b0, b1);
            }
        }
        // stage KV^T halves [d][m/2] (Xq+Xk region; all proj reads done)
#pragma unroll
        for (int rb = 0; rb < 2; rb++)
#pragma unroll
            for (int j = 0; j < 4; j++) {
                int row0 = dt * 32 + rb * 16 + g;
                int w = mq * 16 + j * 4 + t;
                stage[row0 * 68 + w]       = f2h2(acc[rb][j][0], acc[rb][j][1]);
                stage[(row0 + 8) * 68 + w] = f2h2(acc[rb][j][2], acc[rb][j][3]);
            }
    }
    __syncthreads();

    // ---- coalesced store: 64 rows x 16 uint4 ----
    uint4* dst4 = reinterpret_cast<uint4*>(g_kvh) + (size_t)cbase * 1024;
#pragma unroll
    for (int it = 0; it < 4; it++) {
        int i = tid + it * 256;
        int row = i >> 4, q = i & 15;
        dst4[row * 16 + q] = *reinterpret_cast<uint4*>(&stage[row * 68 + q * 4]);
    }
}

// ======================= Kernel 2: exclusive prefix over chunks ==============
// grid BH*4, 256 threads; each thread owns 8 halves (1 uint4); fp32 accum; MLP=4
__global__ void scan_kernel() {
    int bh    = blockIdx.x >> 2;
    int slice = blockIdx.x & 3;
    int tid   = threadIdx.x;
    int base  = slice * 256 + tid;          // uint4 index within chunk (1024/chunk)
    uint4* kv4 = reinterpret_cast<uint4*>(g_kvh);

    float p[8];
#pragma unroll
    for (int j = 0; j < 8; j++) p[j] = 0.f;

    for (int c = 0; c < NCq; c += 4) {
        int i0 = (bh * NCq + c) * 1024 + base;
        uint4 a0 = kv4[i0];
        uint4 a1 = kv4[i0 + 1024];
        uint4 a2 = kv4[i0 + 2048];
        uint4 a3 = kv4[i0 + 3072];
#pragma unroll
        for (int u = 0; u < 4; u++) {
            uint4 a = (u == 0) ? a0 : (u == 1) ? a1 : (u == 2) ? a2 : a3;
            uint4 w;
            w.x = f2h2(p[0], p[1]); w.y = f2h2(p[2], p[3]);
            w.z = f2h2(p[4], p[5]); w.w = f2h2(p[6], p[7]);
            kv4[i0 + u * 1024] = w;
            acc2(p + 0, a.x); acc2(p + 2, a.y);
            acc2(p + 4, a.z); acc2(p + 6, a.w);
        }
    }

    if (slice == 0 && tid < 128) {
        float pk = 0.f;
        for (int c = 0; c < NCq; c += 4) {
            int i0 = (bh * NCq + c) * Mq + tid;
            float a0 = g_ks[i0], a1 = g_ks[i0 + Mq], a2 = g_ks[i0 + 2 * Mq], a3 = g_ks[i0 + 3 * Mq];
            g_ks[i0]          = pk;
            g_ks[i0 + Mq]     = pk + a0;
            g_ks[i0 + 2 * Mq] = pk + a0 + a1;
            g_ks[i0 + 3 * Mq] = pk + a0 + a1 + a2;
            pk += a0 + a1 + a2 + a3;
        }
    }
}

// ======================= Kernel 3: S + num + den(MMA) =======================
// grid BH*NC, 512 threads (16 warps), 74 KB smem, 2 CTAs/SM, 2 syncs.
// smem u32: qp_s [64][68] | kp_s [64][68] | vT [72][36] | kvT [72][68] | Sf [64][36]
// vT row 64 = ones (rowsum S); kvT row 64 = ks (qp.ks) -> den via extra MMA tile.
#define OUT_SMEM ((4352 + 4352 + 2592 + 4896 + 2304) * 4)
__global__ void __launch_bounds__(512, 2) out_kernel(
        const float* __restrict__ Q, float* __restrict__ OUT) {
    extern __shared__ uint32_t sm[];
    uint32_t* qp_s = sm;                // [64][68]
    uint32_t* kp_s = sm + 4352;         // [64][68]
    uint32_t* vT   = sm + 8704;         // [72][36]
    uint32_t* kvT  = sm + 11296;        // [72][68]
    uint32_t* Sfu  = sm + 16192;        // [64][36]
    (void)Q;

    int bid = blockIdx.x;
    int bh = bid / NCq, c = bid % NCq;
    int b = bh / Hq, h = bh % Hq;
    int tid = threadIdx.x;
    int lbase = c * Cq;

    // ---- phase 0: raw fp16 copies ----
    {
        const uint4* qpg = reinterpret_cast<const uint4*>(g_qph) + (size_t)(bh * Lq + lbase) * 16;
        const uint4* kpg = reinterpret_cast<const uint4*>(g_kph) + (size_t)(bh * Lq + lbase) * 16;
        const uint4* kvg = reinterpret_cast<const uint4*>(g_kvh) + (size_t)(bh * NCq + c) * 1024;
        const uint4* vtg = reinterpret_cast<const uint4*>(g_vth) + (size_t)(bh * NCq + c) * 512;
#pragma unroll
        for (int it = 0; it < 2; it++) {
            int i = tid + it * 512;
            int row = i >> 4, q = i & 15;
            *reinterpret_cast<uint4*>(&qp_s[row * 68 + q * 4]) = qpg[row * 16 + q];
            *reinterpret_cast<uint4*>(&kp_s[row * 68 + q * 4]) = kpg[row * 16 + q];
            *reinterpret_cast<uint4*>(&kvT[row * 68 + q * 4])  = kvg[i];
        }
        {
            int row = tid >> 3, q = tid & 7;     // 512 uint4, one each
            *reinterpret_cast<uint4*>(&vT[row * 36 + q * 4]) = vtg[tid];
        }
        // vT rows 64-71: row 64 = ones, rest zero (cols 0-31)
        if (tid < 256) {
            int r = 64 + (tid >> 5), col = tid & 31;
            vT[r * 36 + col] = (r == 64) ? 0x3C003C00u : 0u;
        }
        // kvT row 64 = ks (fp16 pairs); rows 65-71 = 0
        if (tid < 64) {
            int ksb = (bh * NCq + c) * Mq + 2 * tid;
            kvT[64 * 68 + tid] = f2h2(g_ks[ksb], g_ks[ksb + 1]);
        } else if (tid < 512 && tid - 64 < 448) {
            int j = tid - 64;
            int r = 65 + (j >> 6), col = j & 63;
            kvT[r * 68 + col] = 0u;
        }
    }
    __syncthreads();

    int wid = tid >> 5, lane = tid & 31;
    int g = lane >> 2, t = lane & 3;
    int mt = wid & 3, nt = wid >> 2;
    int r0 = mt * 16 + g, r1 = r0 + 8;
    int qr0 = r0 * 68, qr1 = r1 * 68;

    // ---- phase 1: S = qp @ kp^T (K=128), masked -> Sf ----
    {
        float sacc[2][4];
#pragma unroll
        for (int j = 0; j < 2; j++) sacc[j][0] = sacc[j][1] = sacc[j][2] = sacc[j][3] = 0.f;
#pragma unroll
        for (int ks16 = 0; ks16 < 8; ks16++) {
            int kw = ks16 * 8;
            uint32_t a0 = qp_s[qr0 + kw + t];
            uint32_t a1 = qp_s[qr1 + kw + t];
            uint32_t a2 = qp_s[qr0 + kw + t + 4];
            uint32_t a3 = qp_s[qr1 + kw + t + 4];
#pragma unroll
            for (int j = 0; j < 2; j++) {
                int n = nt * 16 + j * 8 + g;
                mma16(sacc[j], a0, a1, a2, a3, kp_s[n * 68 + kw + t], kp_s[n * 68 + kw + t + 4]);
            }
        }
#pragma unroll
        for (int j = 0; j < 2; j++) {
            int cb = nt * 16 + j * 8 + 2 * t;
            int w = nt * 8 + j * 4 + t;
            Sfu[r0 * 36 + w] = f2h2((r0 >= cb) ? sacc[j][0] : 0.f,
                                    (r0 >= cb + 1) ? sacc[j][1] : 0.f);
            Sfu[r1 * 36 + w] = f2h2((r1 >= cb) ? sacc[j][2] : 0.f,
                                    (r1 >= cb + 1) ? sacc[j][3] : 0.f);
        }
    }
    __syncthreads();

    // ---- phase 2: num = S @ v' + qp @ KV' (den rides along as n=64 tile) ----
    float nacc[2][4], dacc[4];
#pragma unroll
    for (int j = 0; j < 2; j++) nacc[j][0] = nacc[j][1] = nacc[j][2] = nacc[j][3] = 0.f;
    dacc[0] = dacc[1] = dacc[2] = dacc[3] = 0.f;

    int sr0 = r0 * 36, sr1 = r1 * 36;
#pragma unroll
    for (int ks16 = 0; ks16 < 4; ks16++) {
        int kw = ks16 * 8;
        uint32_t a0 = Sfu[sr0 + kw + t];
        uint32_t a1 = Sfu[sr1 + kw + t];
        uint32_t a2 = Sfu[sr0 + kw + t + 4];
        uint32_t a3 = Sfu[sr1 + kw + t + 4];
#pragma unroll
        for (int j = 0; j < 2; j++) {
            int n = nt * 16 + j * 8 + g;
            mma16(nacc[j], a0, a1, a2, a3, vT[n * 36 + kw + t], vT[n * 36 + kw + t + 4]);
        }
        mma16(dacc, a0, a1, a2, a3, vT[(64 + g) * 36 + kw + t], vT[(64 + g) * 36 + kw + t + 4]);
    }
#pragma unroll
    for (int ks16 = 0; ks16 < 8; ks16++) {
        int kw = ks16 * 8;
        uint32_t a0 = qp_s[qr0 + kw + t];
        uint32_t a1 = qp_s[qr1 + kw + t];
        uint32_t a2 = qp_s[qr0 + kw + t + 4];
        uint32_t a3 = qp_s[qr1 + kw + t + 4];
#pragma unroll
        for (int j = 0; j < 2; j++) {
            int n = nt * 16 + j * 8 + g;
            mma16(nacc[j], a0, a1, a2, a3, kvT[n * 68 + kw + t], kvT[n * 68 + kw + t + 4]);
        }
        mma16(dacc, a0, a1, a2, a3, kvT[(64 + g) * 68 + kw + t], kvT[(64 + g) * 68 + kw + t + 4]);
    }

    // den lives in t==0 lanes (col 64): broadcast within each quad
    float den0 = __shfl_sync(0xffffffffu, dacc[0], lane & 28);
    float den1 = __shfl_sync(0xffffffffu, dacc[2], lane & 28);
    float i0 = 1.0f / den0;
    float i1 = 1.0f / den1;
    int ob = (b * Lq + lbase) * Hq + h;
#pragma unroll
    for (int j = 0; j < 2; j++) {
        int d = nt * 16 + j * 8 + 2 * t;
        float2 w0 = make_float2(nacc[j][0] * i0, nacc[j][1] * i0);
        float2 w1 = make_float2(nacc[j][2] * i1, nacc[j][3] * i1);
        reinterpret_cast<float2*>(OUT)[((ob + r0 * Hq) * Dq + d) >> 1] = w0;
        reinterpret_cast<float2*>(OUT)[((ob + r1 * Hq) * Dq + d) >> 1] = w1;
    }
}

// ============================ launch ============================
extern "C" void kernel_launch(void* const* d_in, const int* in_sizes, int n_in,
                              void* d_out, int out_size) {
    (void)in_sizes; (void)n_in; (void)out_size;
    const float* Q = (const float*)d_in[0];
    const float* K = (const float*)d_in[1];
    const float* V = (const float*)d_in[2];
    const float* P = (const float*)d_in[3];
    float* OUT = (float*)d_out;

    cudaFuncSetAttribute(chunkkv_kernel, cudaFuncAttributeMaxDynamicSharedMemorySize, CKV_SMEM);
    cudaFuncSetAttribute(out_kernel,     cudaFuncAttributeMaxDynamicSharedMemorySize, OUT_SMEM);

    chunkkv_kernel<<<BHq * NCq, 256, CKV_SMEM>>>(Q, K, V, P);
    scan_kernel<<<BHq * 4, 256>>>();
    out_kernel<<<BHq * NCq, 512, OUT_SMEM>>>(Q, OUT);
}

// round 15
// speedup vs baseline: 1.0261x; 1.0261x over previous
#include <cuda_runtime.h>
#include <cuda_fp16.h>
#include <stdint.h>
#include <math.h>

// Problem constants (fixed by setup_inputs)
#define Bq 2
#define Lq 4096
#define Hq 8
#define Dq 64
#define Mq 128
#define Cq 64
#define NCq (Lq / Cq)      // 64 chunks
#define BHq (Bq * Hq)      // 16 sequences

#define RATIO 0.08838834764831845f   // 1/sqrt(128)
#define STAB  1e-3f

// ---------------- scratch (device globals; no runtime allocation) ----------
__device__ __half g_kvh[BHq * NCq * Dq * Mq];  // [bh, c, d, m] -> exclusive prefix (fp16)
__device__ __half g_kph[BHq * Lq * Mq];        // [bh*L + l][m] fp16
__device__ __half g_vth[BHq * NCq * Dq * Cq];  // [bh, c][d][l] fp16 (raw vT rows)
__device__ float  g_ks[BHq * NCq * Mq];        // [bh, c, m] -> exclusive prefix

// ---------------- helpers ----------------
__device__ __forceinline__ uint32_t f2h2(float lo, float hi) {
    __half2 h = __floats2half2_rn(lo, hi);
    return *reinterpret_cast<uint32_t*>(&h);
}
__device__ __forceinline__ void acc2(float* p, uint32_t u) {
    __half2 h = *reinterpret_cast<__half2*>(&u);
    float2 f = __half22float2(h);
    p[0] += f.x; p[1] += f.y;
}
__device__ __forceinline__ float relu_s(float x) { return fmaxf(x * RATIO, 0.f) + STAB; }

// m16n8k16 fp16 mma, fp32 accumulate (D = A*B + D)
__device__ __forceinline__ void mma16(float* c, uint32_t a0, uint32_t a1, uint32_t a2, uint32_t a3,
                                      uint32_t b0, uint32_t b1) {
    asm("mma.sync.aligned.m16n8k16.row.col.f32.f16.f16.f32 "
        "{%0,%1,%2,%3},{%4,%5,%6,%7},{%8,%9},{%0,%1,%2,%3};"
        : "+f"(c[0]), "+f"(c[1]), "+f"(c[2]), "+f"(c[3])
        : "r"(a0), "r"(a1), "r"(a2), "r"(a3), "r"(b0), "r"(b1));
}

// ======================= Kernel 1: chunk kp -> KV^T / ksum (+exports) =======
// grid BH*NC, 256 threads (8 warps), 54 KB smem, 3 CTAs/SM.  (R13 structure)
// smem u32: Xk [64][36] | Ps [128][36] | kpT [128][36] ([m][l]) | vT [64][36] ([d][l])
// stage (KV^T [64][68]) aliases Xk+Ps after proj.
// Exports: kp fp16 row-major (g_kph, from epilogue regs), vT raw (g_vth).
#define CKV_SMEM ((2304 + 4608 + 4608 + 2304) * 4)
__global__ void __launch_bounds__(256, 3) chunkkv_kernel(
        const float* __restrict__ K, const float* __restrict__ V,
        const float* __restrict__ P) {
    extern __shared__ uint32_t sm[];
    uint32_t* Xk    = sm;               // [64][36]
    uint32_t* Ps    = Xk + 2304;        // [128][36]
    uint32_t* kpT   = Ps + 4608;        // [128][36]
    uint32_t* vT    = kpT + 4608;       // [64][36]
    uint32_t* stage = sm;               // alias [64][68] (free after proj)
    __half*   kph = reinterpret_cast<__half*>(kpT);   // stride 72 halves
    __half*   vTh = reinterpret_cast<__half*>(vT);    // stride 72 halves

    int bid = blockIdx.x;
    int bh = bid / NCq, c = bid % NCq;
    int b = bh / Hq, h = bh % Hq;
    int tid = threadIdx.x;
    int lbase = c * Cq;

    for (int i = tid; i < 128 * 16; i += 256) {
        int m = i >> 4, d4 = i & 15;
        float4 v = reinterpret_cast<const float4*>(P)[m * 16 + d4];
        Ps[m * 36 + d4 * 2]     = f2h2(v.x, v.y);
        Ps[m * 36 + d4 * 2 + 1] = f2h2(v.z, v.w);
    }
    for (int i = tid; i < 64 * 16; i += 256) {
        int l = i >> 4, d4 = i & 15;
        int gidx = ((b * Lq + lbase + l) * Hq + h) * 16 + d4;
        float4 v = reinterpret_cast<const float4*>(K)[gidx];
        Xk[l * 36 + d4 * 2]     = f2h2(v.x, v.y);
        Xk[l * 36 + d4 * 2 + 1] = f2h2(v.z, v.w);
        float4 vv = reinterpret_cast<const float4*>(V)[gidx];
        vTh[(d4 * 4 + 0) * 72 + l] = __float2half_rn(vv.x);
        vTh[(d4 * 4 + 1) * 72 + l] = __float2half_rn(vv.y);
        vTh[(d4 * 4 + 2) * 72 + l] = __float2half_rn(vv.z);
        vTh[(d4 * 4 + 3) * 72 + l] = __float2half_rn(vv.w);
    }
    __syncthreads();

    int wid = tid >> 5, lane = tid & 31;
    int g = lane >> 2, t = lane & 3;
    int cbase = bh * NCq + c;

    // ---- kp = relu(Xk @ P^T) -> kpT [m][l] (STS) + g_kph [l][m] (STG) ----
    {
        uint32_t* kpg = reinterpret_cast<uint32_t*>(g_kph) + (size_t)(bh * Lq + lbase) * 64;
        int lt = wid & 1, nq = wid >> 1;       // 2 row-tiles x 4 col-quarters
        int r0 = lt * 32 + g;
        float acc[2][4][4];
#pragma unroll
        for (int rb = 0; rb < 2; rb++)
#pragma unroll
            for (int j = 0; j < 4; j++)
                acc[rb][j][0] = acc[rb][j][1] = acc[rb][j][2] = acc[rb][j][3] = 0.f;
#pragma unroll
        for (int ks16 = 0; ks16 < 4; ks16++) {
            int kw = ks16 * 8;
            uint32_t a[2][4];
            a[0][0] = Xk[(r0)      * 36 + kw + t];
            a[0][1] = Xk[(r0 + 8)  * 36 + kw + t];
            a[0][2] = Xk[(r0)      * 36 + kw + t + 4];
            a[0][3] = Xk[(r0 + 8)  * 36 + kw + t + 4];
            a[1][0] = Xk[(r0 + 16) * 36 + kw + t];
            a[1][1] = Xk[(r0 + 24) * 36 + kw + t];
            a[1][2] = Xk[(r0 + 16) * 36 + kw + t + 4];
            a[1][3] = Xk[(r0 + 24) * 36 + kw + t + 4];
#pragma unroll
            for (int j = 0; j < 4; j++) {
                int n = nq * 32 + j * 8 + g;
                uint32_t b0 = Ps[n * 36 + kw + t], b1 = Ps[n * 36 + kw + t + 4];
                mma16(acc[0][j], a[0][0], a[0][1], a[0][2], a[0][3], b0, b1);
                mma16(acc[1][j], a[1][0], a[1][1], a[1][2], a[1][3], b0, b1);
            }
        }
#pragma unroll
        for (int rb = 0; rb < 2; rb++)
#pragma unroll
            for (int j = 0; j < 4; j++) {
                int row0 = lt * 32 + rb * 16 + g, row1 = row0 + 8;
                float v0 = relu_s(acc[rb][j][0]), v1 = relu_s(acc[rb][j][1]);
                float v2 = relu_s(acc[rb][j][2]), v3 = relu_s(acc[rb][j][3]);
                int col = nq * 32 + j * 8 + 2 * t;
                kph[col * 72 + row0]       = __float2half_rn(v0);
                kph[(col + 1) * 72 + row0] = __float2half_rn(v1);
                kph[col * 72 + row1]       = __float2half_rn(v2);
                kph[(col + 1) * 72 + row1] = __float2half_rn(v3);
                int colw = nq * 16 + j * 4 + t;
                kpg[row0 * 64 + colw] = f2h2(v0, v1);
                kpg[row1 * 64 + colw] = f2h2(v2, v3);
            }
    }

    // ---- export vT raw (independent of proj; only needs phase-0 fill) ----
    {
        uint4* vtg = reinterpret_cast<uint4*>(g_vth) + (size_t)cbase * 512;
#pragma unroll
        for (int it = 0; it < 2; it++) {
            int i = tid + it * 256;
            int row = i >> 3, q = i & 7;
            vtg[i] = *reinterpret_cast<uint4*>(&vT[row * 36 + q * 4]);
        }
    }
    __syncthreads();

    // ---- ksum[m] = sum_l kp[l][m] ----
    {
        int m = tid >> 1, half = tid & 1;
        float s = 0.f;
        for (int l = 0; l < 32; l++) s += __half2float(kph[m * 72 + half * 32 + l]);
        s += __shfl_xor_sync(0xffffffffu, s, 1);
        if (half == 0) g_ks[cbase * Mq + m] = s;
    }

    // ---- KV^T = v^T @ kp : A = vT [d][l], B = kpT [m][l]; 32x32 tiles ----
    {
        int dt = wid & 1, mq = wid >> 1;
        int d0 = dt * 32 + g;
        float acc[2][4][4];
#pragma unroll
        for (int rb = 0; rb < 2; rb++)
#pragma unroll
            for (int j = 0; j < 4; j++)
                acc[rb][j][0] = acc[rb][j][1] = acc[rb][j][2] = acc[rb][j][3] = 0.f;
#pragma unroll
        for (int ks16 = 0; ks16 < 4; ks16++) {
            int kw = ks16 * 8;
            uint32_t a[2][4];
            a[0][0] = vT[(d0)      * 36 + kw + t];
            a[0][1] = vT[(d0 + 8)  * 36 + kw + t];
            a[0][2] = vT[(d0)      * 36 + kw + t + 4];
            a[0][3] = vT[(d0 + 8)  * 36 + kw + t + 4];
            a[1][0] = vT[(d0 + 16) * 36 + kw + t];
            a[1][1] = vT[(d0 + 24) * 36 + kw + t];
            a[1][2] = vT[(d0 + 16) * 36 + kw + t + 4];
            a[1][3] = vT[(d0 + 24) * 36 + kw + t + 4];
#pragma unroll
            for (int j = 0; j < 4; j++) {
                int n = mq * 32 + j * 8 + g;
                uint32_t b0 = kpT[n * 36 + kw + t], b1 = kpT[n * 36 + kw + t + 4];
                mma16(acc[0][j], a[0][0], a[0][1], a[0][2], a[0][3], b0, b1);
                mma16(acc[1][j], a[1][0], a[1][1], a[1][2], a[1][3], b0, b1);
            }
        }
#pragma unroll
        for (int rb = 0; rb < 2; rb++)
#pragma unroll
            for (int j = 0; j < 4; j++) {
                int row0 = dt * 32 + rb * 16 + g;
                int w = mq * 16 + j * 4 + t;
                stage[row0 * 68 + w]       = f2h2(acc[rb][j][0], acc[rb][j][1]);
                stage[(row0 + 8) * 68 + w] = f2h2(acc[rb][j][2], acc[rb][j][3]);
            }
    }
    __syncthreads();

    // ---- coalesced store KV^T ----
    uint4* dst4 = reinterpret_cast<uint4*>(g_kvh) + (size_t)cbase * 1024;
#pragma unroll
    for (int it = 0; it < 4; it++) {
        int i = tid + it * 256;
        int row = i >> 4, q = i & 15;
        dst4[row * 16 + q] = *reinterpret_cast<uint4*>(&stage[row * 68 + q * 4]);
    }
}

// ======================= Kernel 2: exclusive prefix over chunks ==============
__global__ void scan_kernel() {
    int bh    = blockIdx.x >> 2;
    int slice = blockIdx.x & 3;
    int tid   = threadIdx.x;
    int base  = slice * 256 + tid;
    uint4* kv4 = reinterpret_cast<uint4*>(g_kvh);

    float p[8];
#pragma unroll
    for (int j = 0; j < 8; j++) p[j] = 0.f;

    for (int c = 0; c < NCq; c += 4) {
        int i0 = (bh * NCq + c) * 1024 + base;
        uint4 a0 = kv4[i0];
        uint4 a1 = kv4[i0 + 1024];
        uint4 a2 = kv4[i0 + 2048];
        uint4 a3 = kv4[i0 + 3072];
#pragma unroll
        for (int u = 0; u < 4; u++) {
            uint4 a = (u == 0) ? a0 : (u == 1) ? a1 : (u == 2) ? a2 : a3;
            uint4 w;
            w.x = f2h2(p[0], p[1]); w.y = f2h2(p[2], p[3]);
            w.z = f2h2(p[4], p[5]); w.w = f2h2(p[6], p[7]);
            kv4[i0 + u * 1024] = w;
            acc2(p + 0, a.x); acc2(p + 2, a.y);
            acc2(p + 4, a.z); acc2(p + 6, a.w);
        }
    }

    if (slice == 0 && tid < 128) {
        float pk = 0.f;
        for (int c = 0; c < NCq; c += 4) {
            int i0 = (bh * NCq + c) * Mq + tid;
            float a0 = g_ks[i0], a1 = g_ks[i0 + Mq], a2 = g_ks[i0 + 2 * Mq], a3 = g_ks[i0 + 3 * Mq];
            g_ks[i0]          = pk;
            g_ks[i0 + Mq]     = pk + a0;
            g_ks[i0 + 2 * Mq] = pk + a0 + a1;
            g_ks[i0 + 3 * Mq] = pk + a0 + a1 + a2;
            pk += a0 + a1 + a2 + a3;
        }
    }
}

// ======================= Kernel 3: qp proj + S + num/den(MMA) ===============
// grid BH*NC, 512 threads (16 warps), ~92 KB smem, 2 CTAs/SM, 3 syncs.
// smem u32: Xq [64][36] (-> Sf) | Ps [128][36] | qp_s [64][68] | kp_s [64][68]
//           | vT [72][36] | kvT [72][68]
// vT row 64 = ones (rowsum S); kvT row 64 = ks -> den via extra MMA tile.
#define OUT_SMEM ((2304 + 4608 + 4352 + 4352 + 2592 + 4896) * 4)
__global__ void __launch_bounds__(512, 2) out_kernel(
        const float* __restrict__ Q, const float* __restrict__ P,
        float* __restrict__ OUT) {
    extern __shared__ uint32_t sm[];
    uint32_t* Xq   = sm;                // [64][36] -> Sf after proj
    uint32_t* Ps   = sm + 2304;         // [128][36]
    uint32_t* qp_s = sm + 6912;         // [64][68]
    uint32_t* kp_s = sm + 11264;        // [64][68]
    uint32_t* vT   = sm + 15616;        // [72][36]
    uint32_t* kvT  = sm + 18208;        // [72][68]
    uint32_t* Sfu  = Xq;                // alias

    int bid = blockIdx.x;
    int bh = bid / NCq, c = bid % NCq;
    int b = bh / Hq, h = bh % Hq;
    int tid = threadIdx.x;
    int lbase = c * Cq;

    // ---- phase 0: fills (convert Q,P; raw copies kp, kv, vT; ks/ones rows) ----
    for (int i = tid; i < 128 * 16; i += 512) {
        int m = i >> 4, d4 = i & 15;
        float4 v = reinterpret_cast<const float4*>(P)[m * 16 + d4];
        Ps[m * 36 + d4 * 2]     = f2h2(v.x, v.y);
        Ps[m * 36 + d4 * 2 + 1] = f2h2(v.z, v.w);
    }
    for (int i = tid; i < 64 * 16; i += 512) {
        int l = i >> 4, d4 = i & 15;
        float4 q = reinterpret_cast<const float4*>(Q)[((b * Lq + lbase + l) * Hq + h) * 16 + d4];
        Xq[l * 36 + d4 * 2]     = f2h2(q.x, q.y);
        Xq[l * 36 + d4 * 2 + 1] = f2h2(q.z, q.w);
    }
    {
        const uint4* kpg = reinterpret_cast<const uint4*>(g_kph) + (size_t)(bh * Lq + lbase) * 16;
        const uint4* kvg = reinterpret_cast<const uint4*>(g_kvh) + (size_t)(bh * NCq + c) * 1024;
        const uint4* vtg = reinterpret_cast<const uint4*>(g_vth) + (size_t)(bh * NCq + c) * 512;
#pragma unroll
        for (int it = 0; it < 2; it++) {
            int i = tid + it * 512;
            int row = i >> 4, q = i & 15;
            *reinterpret_cast<uint4*>(&kp_s[row * 68 + q * 4]) = kpg[row * 16 + q];
            *reinterpret_cast<uint4*>(&kvT[row * 68 + q * 4])  = kvg[i];
        }
        {
            int row = tid >> 3, q = tid & 7;
            *reinterpret_cast<uint4*>(&vT[row * 36 + q * 4]) = vtg[tid];
        }
        if (tid < 256) {
            int r = 64 + (tid >> 5), col = tid & 31;
            vT[r * 36 + col] = (r == 64) ? 0x3C003C00u : 0u;
        }
        if (tid < 64) {
            int ksb = (bh * NCq + c) * Mq + 2 * tid;
            kvT[64 * 68 + tid] = f2h2(g_ks[ksb], g_ks[ksb + 1]);
        } else if (tid - 64 < 448) {
            int j = tid - 64;
            int r = 65 + (j >> 6), col = j & 63;
            kvT[r * 68 + col] = 0u;
        }
    }
    __syncthreads();

    int wid = tid >> 5, lane = tid & 31;
    int g = lane >> 2, t = lane & 3;

    // ---- phase 1: qp = relu(Xq @ P^T); 16 warps: 4 row-tiles x 4 col-tiles ----
    {
        int mt = wid & 3, nq = wid >> 2;
        int r0 = mt * 16 + g, r1 = r0 + 8;
        float acc[4][4];
#pragma unroll
        for (int j = 0; j < 4; j++) acc[j][0] = acc[j][1] = acc[j][2] = acc[j][3] = 0.f;
#pragma unroll
        for (int ks16 = 0; ks16 < 4; ks16++) {
            int kw = ks16 * 8;
            uint32_t a0 = Xq[r0 * 36 + kw + t];
            uint32_t a1 = Xq[r1 * 36 + kw + t];
            uint32_t a2 = Xq[r0 * 36 + kw + t + 4];
            uint32_t a3 = Xq[r1 * 36 + kw + t + 4];
#pragma unroll
            for (int j = 0; j < 4; j++) {
                int n = nq * 32 + j * 8 + g;
                mma16(acc[j], a0, a1, a2, a3, Ps[n * 36 + kw + t], Ps[n * 36 + kw + t + 4]);
            }
        }
#pragma unroll
        for (int j = 0; j < 4; j++) {
            int colw = nq * 16 + j * 4 + t;
            qp_s[r0 * 68 + colw] = f2h2(relu_s(acc[j][0]), relu_s(acc[j][1]));
            qp_s[r1 * 68 + colw] = f2h2(relu_s(acc[j][2]), relu_s(acc[j][3]));
        }
    }
    __syncthreads();

    int mt = wid & 3, nt = wid >> 2;
    int r0 = mt * 16 + g, r1 = r0 + 8;
    int qr0 = r0 * 68, qr1 = r1 * 68;

    // ---- phase 2: S = qp @ kp^T (K=128), masked -> Sf (Xq region) ----
    {
        float sacc[2][4];
#pragma unroll
        for (int j = 0; j < 2; j++) sacc[j][0] = sacc[j][1] = sacc[j][2] = sacc[j][3] = 0.f;
#pragma unroll
        for (int ks16 = 0; ks16 < 8; ks16++) {
            int kw = ks16 * 8;
            uint32_t a0 = qp_s[qr0 + kw + t];
            uint32_t a1 = qp_s[qr1 + kw + t];
            uint32_t a2 = qp_s[qr0 + kw + t + 4];
            uint32_t a3 = qp_s[qr1 + kw + t + 4];
#pragma unroll
            for (int j = 0; j < 2; j++) {
                int n = nt * 16 + j * 8 + g;
                mma16(sacc[j], a0, a1, a2, a3, kp_s[n * 68 + kw + t], kp_s[n * 68 + kw + t + 4]);
            }
        }
#pragma unroll
        for (int j = 0; j < 2; j++) {
            int cb = nt * 16 + j * 8 + 2 * t;
            int w = nt * 8 + j * 4 + t;
            Sfu[r0 * 36 + w] = f2h2((r0 >= cb) ? sacc[j][0] : 0.f,
                                    (r0 >= cb + 1) ? sacc[j][1] : 0.f);
            Sfu[r1 * 36 + w] = f2h2((r1 >= cb) ? sacc[j][2] : 0.f,
                                    (r1 >= cb + 1) ? sacc[j][3] : 0.f);
        }
    }
    __syncthreads();

    // ---- phase 3: num = S @ v' + qp @ KV' (den = extra n=64 tile) ----
    float nacc[2][4], dacc[4];
#pragma unroll
    for (int j = 0; j < 2; j++) nacc[j][0] = nacc[j][1] = nacc[j][2] = nacc[j][3] = 0.f;
    dacc[0] = dacc[1] = dacc[2] = dacc[3] = 0.f;

    int sr0 = r0 * 36, sr1 = r1 * 36;
#pragma unroll
    for (int ks16 = 0; ks16 < 4; ks16++) {
        int kw = ks16 * 8;
        uint32_t a0 = Sfu[sr0 + kw + t];
        uint32_t a1 = Sfu[sr1 + kw + t];
        uint32_t a2 = Sfu[sr0 + kw + t + 4];
        uint32_t a3 = Sfu[sr1 + kw + t + 4];
#pragma unroll
        for (int j = 0; j < 2; j++) {
            int n = nt * 16 + j * 8 + g;
            mma16(nacc[j], a0, a1, a2, a3, vT[n * 36 + kw + t], vT[n * 36 + kw + t + 4]);
        }
        mma16(dacc, a0, a1, a2, a3, vT[(64 + g) * 36 + kw + t], vT[(64 + g) * 36 + kw + t + 4]);
    }
#pragma unroll
    for (int ks16 = 0; ks16 < 8; ks16++) {
        int kw = ks16 * 8;
        uint32_t a0 = qp_s[qr0 + kw + t];
        uint32_t a1 = qp_s[qr1 + kw + t];
        uint32_t a2 = qp_s[qr0 + kw + t + 4];
        uint32_t a3 = qp_s[qr1 + kw + t + 4];
#pragma unroll
        for (int j = 0; j < 2; j++) {
            int n = nt * 16 + j * 8 + g;
            mma16(nacc[j], a0, a1, a2, a3, kvT[n * 68 + kw + t], kvT[n * 68 + kw + t + 4]);
        }
        mma16(dacc, a0, a1, a2, a3, kvT[(64 + g) * 68 + kw + t], kvT[(64 + g) * 68 + kw + t + 4]);
    }

    // den in t==0 lanes (col 64): broadcast within each quad
    float den0 = __shfl_sync(0xffffffffu, dacc[0], lane & 28);
    float den1 = __shfl_sync(0xffffffffu, dacc[2], lane & 28);
    float i0 = 1.0f / den0;
    float i1 = 1.0f / den1;
    int ob = (b * Lq + lbase) * Hq + h;
#pragma unroll
    for (int j = 0; j < 2; j++) {
        int d = nt * 16 + j * 8 + 2 * t;
        float2 w0 = make_float2(nacc[j][0] * i0, nacc[j][1] * i0);
        float2 w1 = make_float2(nacc[j][2] * i1, nacc[j][3] * i1);
        reinterpret_cast<float2*>(OUT)[((ob + r0 * Hq) * Dq + d) >> 1] = w0;
        reinterpret_cast<float2*>(OUT)[((ob + r1 * Hq) * Dq + d) >> 1] = w1;
    }
}

// ============================ launch ============================
extern "C" void kernel_launch(void* const* d_in, const int* in_sizes, int n_in,
                              void* d_out, int out_size) {
    (void)in_sizes; (void)n_in; (void)out_size;
    const float* Q = (const float*)d_in[0];
    const float* K = (const float*)d_in[1];
    const float* V = (const float*)d_in[2];
    const float* P = (const float*)d_in[3];
    float* OUT = (float*)d_out;

    cudaFuncSetAttribute(chunkkv_kernel, cudaFuncAttributeMaxDynamicSharedMemorySize, CKV_SMEM);
    cudaFuncSetAttribute(out_kernel,     cudaFuncAttributeMaxDynamicSharedMemorySize, OUT_SMEM);

    chunkkv_kernel<<<BHq * NCq, 256, CKV_SMEM>>>(K, V, P);
    scan_kernel<<<BHq * 4, 256>>>();
    out_kernel<<<BHq * NCq, 512, OUT_SMEM>>>(Q, P, OUT);
}